// round 13
// baseline (speedup 1.0000x reference)
#include <cuda_runtime.h>

#define M_TOTAL 2048
#define IN_DIM  4096
#define OUT_DIM 4096
#define NB      16
#define RANK    16
#define BLK     256
#define NQ      4             // quarter strips of 64 p

typedef unsigned long long u64;

// Scratch (__device__ globals per allocation rules)
__device__ float g_T[NQ * NB * RANK * M_TOTAL];   // [qt][ib][r][m]  8 MB, m contiguous
__device__ float g_Z[NB * RANK * M_TOTAL];        // [o][r][m]       2 MB, m contiguous
__device__ float g_rsp[M_TOTAL * NB * NQ];        // [m][ib*4+qt]    1 MB

// ---------- f32x2 packed helpers ----------
__device__ __forceinline__ u64 pack2(float lo, float hi) {
    u64 r; asm("mov.b64 %0, {%1, %2};" : "=l"(r) : "f"(lo), "f"(hi)); return r;
}
__device__ __forceinline__ void unpack2(u64 p, float& lo, float& hi) {
    asm("mov.b64 {%0, %1}, %2;" : "=f"(lo), "=f"(hi) : "l"(p));
}
__device__ __forceinline__ void ffma2(u64& d, u64 a, u64 b) {
    asm("fma.rn.f32x2 %0, %1, %2, %0;" : "+l"(d) : "l"(a), "l"(b));
}
__device__ __forceinline__ void fadd2(u64& d, u64 a) {
    asm("add.rn.f32x2 %0, %0, %1;" : "+l"(d) : "l"(a));
}

// ---------- cp.async helpers ----------
__device__ __forceinline__ unsigned smem_u32(const void* p) {
    unsigned a;
    asm("{ .reg .u64 t; cvta.to.shared.u64 t, %1; cvt.u32.u64 %0, t; }" : "=r"(a) : "l"(p));
    return a;
}
__device__ __forceinline__ void cp_async16(unsigned dst, const void* src) {
    asm volatile("cp.async.ca.shared.global [%0], [%1], 16;" :: "r"(dst), "l"(src));
}
__device__ __forceinline__ void cp_commit() {
    asm volatile("cp.async.commit_group;");
}
__device__ __forceinline__ void cp_wait1() {
    asm volatile("cp.async.wait_group 1;");
}
__device__ __forceinline__ void cp_wait0() {
    asm volatile("cp.async.wait_group 0;");
}

// ================= Kernel A: persistent, double-buffered =================
// CTA = one (ib,qt) strip x 512 rows, walked as 4 tiles of 128 rows.
// Tile t+1's ENTIRE 34.8 KB x-fill streams in while tile t computes.
#define ROWS_A  128
#define PSTR    68            // 64 + 4 pad floats
#define NTILES  4
#define XS_FLOATS (ROWS_A * PSTR)

__global__ void __launch_bounds__(256)
kernelA(const float* __restrict__ x, const float* __restrict__ Vt)
{
    extern __shared__ float sm[];
    float* xsbuf[2] = { sm, sm + XS_FLOATS };          // 2 x 34.8 KB
    u64*   vts2 = (u64*)(sm + 2 * XS_FLOATS);          // [p2][r] 4 KB

    const int qt    = blockIdx.x & 3;
    const int ib    = blockIdx.x >> 2;
    const int rbase = blockIdx.y * (NTILES * ROWS_A);  // 512-row strip
    const int tid   = threadIdx.x;

    const float4* xg4 = (const float4*)x;
    unsigned xs_b[2] = { smem_u32(xsbuf[0]), smem_u32(xsbuf[1]) };

    auto fill = [&](int t) {                            // one group = whole tile
        unsigned base = xs_b[t & 1];
        int row0 = rbase + t * ROWS_A;
        #pragma unroll
        for (int k = 0; k < 8; ++k) {
            int idx = tid + k * 256;          // 0..2047
            int m   = idx >> 4;
            int c4  = idx & 15;
            const float4* src = xg4 + ((size_t)(row0 + m) * (IN_DIM / 4)
                                       + ib * 64 + qt * 16 + c4);
            cp_async16(base + (m * PSTR + c4 * 4) * 4, src);
        }
        cp_commit();
    };

    fill(0);                                   // group 0

    // Stage Vt pairs while fill(0) streams
    #pragma unroll
    for (int k = 0; k < 2; ++k) {
        int p2 = (tid >> 4) + k * 16;          // 0..31
        int r  = tid & 15;
        const float* vg = Vt + ((size_t)ib * BLK + qt * 64 + 2 * p2) * RANK + r;
        vts2[p2 * 16 + r] = pack2(vg[0], vg[RANK]);
    }

    fill(1);                                   // group 1

    const int mg = tid & 127;
    const int rg = tid >> 7;                   // warp-uniform rank half
    const int r0 = rg * 8;

    #pragma unroll
    for (int t = 0; t < NTILES; ++t) {
        if (t < NTILES - 1) cp_wait1();        // tile t's group complete
        else                cp_wait0();
        __syncthreads();

        const float* xr = xsbuf[t & 1] + mg * PSTR;
        const int row0 = rbase + t * ROWS_A;

        u64 acc[8];
        #pragma unroll
        for (int k = 0; k < 8; ++k) acc[k] = 0ULL;
        u64 rs = 0ULL;

        #pragma unroll
        for (int p4 = 0; p4 < 16; ++p4) {
            ulonglong2 xa = *(const ulonglong2*)(xr + p4 * 4);   // (p0,p1),(p2,p3)
            if (rg == 0) { fadd2(rs, xa.x); fadd2(rs, xa.y); }
            const u64* v0 = vts2 + (2 * p4) * 16 + r0;
            {
                ulonglong2 a = *(const ulonglong2*)(v0);
                ulonglong2 b = *(const ulonglong2*)(v0 + 2);
                ulonglong2 c = *(const ulonglong2*)(v0 + 4);
                ulonglong2 d = *(const ulonglong2*)(v0 + 6);
                ffma2(acc[0], xa.x, a.x); ffma2(acc[1], xa.x, a.y);
                ffma2(acc[2], xa.x, b.x); ffma2(acc[3], xa.x, b.y);
                ffma2(acc[4], xa.x, c.x); ffma2(acc[5], xa.x, c.y);
                ffma2(acc[6], xa.x, d.x); ffma2(acc[7], xa.x, d.y);
            }
            const u64* v1 = v0 + 16;
            {
                ulonglong2 a = *(const ulonglong2*)(v1);
                ulonglong2 b = *(const ulonglong2*)(v1 + 2);
                ulonglong2 c = *(const ulonglong2*)(v1 + 4);
                ulonglong2 d = *(const ulonglong2*)(v1 + 6);
                ffma2(acc[0], xa.y, a.x); ffma2(acc[1], xa.y, a.y);
                ffma2(acc[2], xa.y, b.x); ffma2(acc[3], xa.y, b.y);
                ffma2(acc[4], xa.y, c.x); ffma2(acc[5], xa.y, c.y);
                ffma2(acc[6], xa.y, d.x); ffma2(acc[7], xa.y, d.y);
            }
        }

        // Store T tile: [qt][ib][r][m] -> coalesced STG.32 per rank
        {
            float* base = g_T + ((size_t)((qt * NB + ib) * RANK)) * M_TOTAL + row0 + mg;
            #pragma unroll
            for (int k = 0; k < 8; ++k) {
                float lo, hi;
                unpack2(acc[k], lo, hi);
                base[(size_t)(r0 + k) * M_TOTAL] = lo + hi;
            }
        }
        if (rg == 0) {
            float lo, hi;
            unpack2(rs, lo, hi);
            g_rsp[(size_t)(row0 + mg) * (NB * NQ) + ib * NQ + qt] = lo + hi;
        }

        __syncthreads();                       // everyone done reading buffer t&1
        if (t + 2 < NTILES) fill(t + 2);       // refill it for tile t+2
    }
}

// ================= Kernel Z =================
// For each rank r: Z_r[o][m] = sum_i S[o][i][r] * (sum_qt T_qt)[i][r][m]
__global__ void __launch_bounds__(256)
kernelZ(const float* __restrict__ S)
{
    __shared__ float Ts[NB * 256];     // [i][m] 16 KB
    __shared__ float Ss[8 * NB];       // S[o][i] at this r, 8 o's

    const int r   = blockIdx.x;
    const int oh  = blockIdx.y & 1;    // o-half
    const int m0  = (blockIdx.y >> 1) * 256;
    const int tid = threadIdx.x;

    if (tid < 128) {
        int o = oh * 8 + (tid >> 4);
        int i = tid & 15;
        Ss[tid] = S[(o * NB + i) * RANK + r];
    }

    const float4* gT4 = (const float4*)g_T;
    const size_t qs = (size_t)NB * RANK * (M_TOTAL / 4);   // float4 per quarter
    #pragma unroll
    for (int k = 0; k < 4; ++k) {
        int idx = tid + k * 256;       // 0..1023 over i(16) x c4(64)
        int i   = idx >> 6;
        int c4  = idx & 63;
        size_t base = ((size_t)i * RANK + r) * (M_TOTAL / 4) + (m0 / 4) + c4;
        float4 a = gT4[base];
        #pragma unroll
        for (int q = 1; q < NQ; ++q) {
            float4 b = gT4[base + q * qs];
            a.x += b.x; a.y += b.y; a.z += b.z; a.w += b.w;
        }
        ((float4*)(Ts + i * 256))[c4] = a;
    }
    __syncthreads();

    float t[NB];
    #pragma unroll
    for (int i = 0; i < NB; ++i) t[i] = Ts[i * 256 + tid];   // conflict-free

    #pragma unroll
    for (int oo = 0; oo < 8; ++oo) {
        float z = 0.f;
        #pragma unroll
        for (int i = 0; i < NB; ++i) z = fmaf(t[i], Ss[oo * 16 + i], z);
        g_Z[((size_t)((oh * 8 + oo) * RANK + r)) * M_TOTAL + m0 + tid] = z;  // coalesced
    }
}

// ================= Kernel B: out = Z @ U + (1+rowsum)*bias =================
#define ROWS_B  32
#define ZS2     34      // u64 stride (even -> 16B-aligned ull2 loads)

__global__ void __launch_bounds__(256)
kernelB(const float* __restrict__ U, const float* __restrict__ bias,
        float* __restrict__ out)
{
    __shared__ float Us[RANK * BLK];       // 16 KB
    __shared__ u64   Zt2[RANK * ZS2];      // (z,z) duplicated pairs, [r][m]
    __shared__ float rs[ROWS_B];

    const int o    = blockIdx.x;
    const int row0 = blockIdx.y * ROWS_B;
    const int tid  = threadIdx.x;

    const float4* Ug4 = (const float4*)(U + (size_t)o * (RANK * BLK));
    #pragma unroll
    for (int i = tid; i < 1024; i += 256) ((float4*)Us)[i] = Ug4[i];

    // Zt2 fill from g_Z[o][r][m] (m-contiguous)
    {
        int r = tid >> 5;         // 0..7
        int m = tid & 31;
        float z0 = g_Z[((size_t)(o * RANK + r))     * M_TOTAL + row0 + m];
        float z1 = g_Z[((size_t)(o * RANK + r + 8)) * M_TOTAL + row0 + m];
        Zt2[r * ZS2 + m]       = pack2(z0, z0);
        Zt2[(r + 8) * ZS2 + m] = pack2(z1, z1);
    }
    if (tid < ROWS_B) {
        const float4* rp = (const float4*)(g_rsp + (size_t)(row0 + tid) * (NB * NQ));
        float s = 1.0f;
        #pragma unroll
        for (int c = 0; c < 16; ++c) {
            float4 v = rp[c];
            s += (v.x + v.y) + (v.z + v.w);
        }
        rs[tid] = s;
    }
    __syncthreads();

    const int mg = tid >> 5;        // 0..7 -> rows m0..m0+3
    const int qg = tid & 31;        // q = qg*4 and 128+qg*4
    const int m0 = mg * 4;

    const float4* b4 = (const float4*)bias;
    float4 ba = b4[o * 64 + qg];
    float4 bb = b4[o * 64 + 32 + qg];

    ulonglong2 Aa[4], Ab[4];
    #pragma unroll
    for (int j = 0; j < 4; ++j) {
        float r = rs[m0 + j];
        Aa[j].x = pack2(r * ba.x, r * ba.y);
        Aa[j].y = pack2(r * ba.z, r * ba.w);
        Ab[j].x = pack2(r * bb.x, r * bb.y);
        Ab[j].y = pack2(r * bb.z, r * bb.w);
    }

    #pragma unroll
    for (int r = 0; r < RANK; ++r) {
        const u64* zp = Zt2 + r * ZS2 + m0;
        ulonglong2 z01 = *(const ulonglong2*)(zp);       // broadcast LDS.128
        ulonglong2 z23 = *(const ulonglong2*)(zp + 2);
        u64 q0 = z01.x, q1 = z01.y, q2 = z23.x, q3 = z23.y;
        ulonglong2 ua = *(const ulonglong2*)(Us + r * 256 + qg * 4);
        ulonglong2 ub = *(const ulonglong2*)(Us + r * 256 + 128 + qg * 4);
        ffma2(Aa[0].x, q0, ua.x); ffma2(Aa[0].y, q0, ua.y);
        ffma2(Ab[0].x, q0, ub.x); ffma2(Ab[0].y, q0, ub.y);
        ffma2(Aa[1].x, q1, ua.x); ffma2(Aa[1].y, q1, ua.y);
        ffma2(Ab[1].x, q1, ub.x); ffma2(Ab[1].y, q1, ub.y);
        ffma2(Aa[2].x, q2, ua.x); ffma2(Aa[2].y, q2, ua.y);
        ffma2(Ab[2].x, q2, ub.x); ffma2(Ab[2].y, q2, ub.y);
        ffma2(Aa[3].x, q3, ua.x); ffma2(Aa[3].y, q3, ua.y);
        ffma2(Ab[3].x, q3, ub.x); ffma2(Ab[3].y, q3, ub.y);
    }

    size_t ob = (size_t)(row0 + m0) * OUT_DIM + o * 256 + qg * 4;
    #pragma unroll
    for (int j = 0; j < 4; ++j) {
        *(ulonglong2*)(out + ob + (size_t)j * OUT_DIM)       = Aa[j];
        *(ulonglong2*)(out + ob + (size_t)j * OUT_DIM + 128) = Ab[j];
    }
}

extern "C" void kernel_launch(void* const* d_in, const int* in_sizes, int n_in,
                              void* d_out, int out_size)
{
    const float* x    = (const float*)d_in[0];
    const float* S    = (const float*)d_in[1];
    const float* U    = (const float*)d_in[2];
    const float* Vt   = (const float*)d_in[3];
    const float* bias = (const float*)d_in[4];
    float* out = (float*)d_out;

    const int smA = (2 * XS_FLOATS) * (int)sizeof(float) + (64 / 2) * RANK * (int)sizeof(u64);
    cudaFuncSetAttribute(kernelA, cudaFuncAttributeMaxDynamicSharedMemorySize, smA);

    kernelA<<<dim3(NB * NQ, M_TOTAL / (NTILES * ROWS_A)), 256, smA>>>(x, Vt);
    kernelZ<<<dim3(RANK, 16), 256>>>(S);
    kernelB<<<dim3(NB, M_TOTAL / ROWS_B), 256>>>(U, bias, out);
}

// round 14
// speedup vs baseline: 1.0063x; 1.0063x over previous
#include <cuda_runtime.h>

#define M_TOTAL 2048
#define IN_DIM  4096
#define OUT_DIM 4096
#define NB      16
#define RANK    16
#define BLK     256
#define NQ      8             // eighth strips of 32 p
#define KA      32

typedef unsigned long long u64;

// Scratch (__device__ globals per allocation rules)
__device__ float g_T[NQ * NB * RANK * M_TOTAL];   // [qt][ib][r][m]  16 MB, m contiguous
__device__ float g_Z[NB * RANK * M_TOTAL];        // [o][r][m]       2 MB, m contiguous
__device__ float g_rsp[M_TOTAL * NB * NQ];        // [m][ib*8+qt]    1 MB

// ---------- f32x2 packed helpers ----------
__device__ __forceinline__ u64 pack2(float lo, float hi) {
    u64 r; asm("mov.b64 %0, {%1, %2};" : "=l"(r) : "f"(lo), "f"(hi)); return r;
}
__device__ __forceinline__ void unpack2(u64 p, float& lo, float& hi) {
    asm("mov.b64 {%0, %1}, %2;" : "=f"(lo), "=f"(hi) : "l"(p));
}
__device__ __forceinline__ void ffma2(u64& d, u64 a, u64 b) {
    asm("fma.rn.f32x2 %0, %1, %2, %0;" : "+l"(d) : "l"(a), "l"(b));
}
__device__ __forceinline__ void fadd2(u64& d, u64 a) {
    asm("add.rn.f32x2 %0, %0, %1;" : "+l"(d) : "l"(a));
}

// ---------- cp.async helpers ----------
__device__ __forceinline__ unsigned smem_u32(const void* p) {
    unsigned a;
    asm("{ .reg .u64 t; cvta.to.shared.u64 t, %1; cvt.u32.u64 %0, t; }" : "=r"(a) : "l"(p));
    return a;
}
__device__ __forceinline__ void cp_async16(unsigned dst, const void* src) {
    asm volatile("cp.async.ca.shared.global [%0], [%1], 16;" :: "r"(dst), "l"(src));
}
__device__ __forceinline__ void cp_commit() {
    asm volatile("cp.async.commit_group;");
}
__device__ __forceinline__ void cp_wait0() {
    asm volatile("cp.async.wait_group 0;");
}

// ================= Kernel A =================
// R10 recipe (one cp.async burst, one barrier, grid 1024, smem 39KB) with a
// denser 4-rows x 4-ranks register tile: 18 wavefronts / 64 FFMA2 per iter.
#define ROWS_A  256
#define PSTR    36            // 32 + 4 pad floats; conflict-free LDS.128

__global__ void __launch_bounds__(256)
kernelA(const float* __restrict__ x, const float* __restrict__ Vt)
{
    __shared__ float xs[ROWS_A * PSTR];        // 36.9 KB
    __shared__ u64   vts2[(KA / 2) * RANK];    // [p2][r] 2 KB

    const int qt   = blockIdx.x & 7;           // eighth 0..7 (p offset qt*32)
    const int ib   = blockIdx.x >> 3;          // input block
    const int row0 = blockIdx.y * ROWS_A;
    const int tid  = threadIdx.x;

    // 1) Issue ALL x fills immediately (one group, 2048 float4s = 32 KB)
    const float4* xg4 = (const float4*)x;
    unsigned xs_base = smem_u32(xs);
    #pragma unroll
    for (int k = 0; k < 8; ++k) {
        int idx = tid + k * 256;          // 0..2047
        int m   = idx >> 3;
        int c4  = idx & 7;
        const float4* src = xg4 + ((size_t)(row0 + m) * (IN_DIM / 4)
                                   + ib * 64 + qt * 8 + c4);
        cp_async16(xs_base + (m * PSTR + c4 * 4) * 4, src);
    }
    cp_commit();

    // 2) Stage Vt pairs while the async fill streams in
    {
        int p2 = tid >> 4;                // 0..15
        int r  = tid & 15;
        const float* vg = Vt + ((size_t)ib * BLK + qt * KA + 2 * p2) * RANK + r;
        vts2[p2 * 16 + r] = pack2(vg[0], vg[RANK]);
    }

    cp_wait0();
    __syncthreads();                      // the ONLY barrier

    // 3) Compute: 4 rows x 4 ranks per thread, f32x2 over p, 8 p4-iters
    const int mg = tid & 63;              // rows mg, +64, +128, +192
    const int rg = tid >> 6;              // 0..3 warp-uniform -> ranks rg*4..+3
    const int r0 = rg * 4;
    const float* xr0 = xs + mg * PSTR;
    const float* xr1 = xs + (mg + 64) * PSTR;
    const float* xr2 = xs + (mg + 128) * PSTR;
    const float* xr3 = xs + (mg + 192) * PSTR;

    u64 a0[4], a1[4], a2[4], a3[4];
    #pragma unroll
    for (int k = 0; k < 4; ++k) { a0[k] = 0ULL; a1[k] = 0ULL; a2[k] = 0ULL; a3[k] = 0ULL; }
    u64 rs0 = 0ULL, rs1 = 0ULL, rs2 = 0ULL, rs3 = 0ULL;

    #pragma unroll
    for (int p4 = 0; p4 < 8; ++p4) {
        ulonglong2 x0 = *(const ulonglong2*)(xr0 + p4 * 4);   // (p0,p1),(p2,p3)
        ulonglong2 x1 = *(const ulonglong2*)(xr1 + p4 * 4);
        ulonglong2 x2 = *(const ulonglong2*)(xr2 + p4 * 4);
        ulonglong2 x3 = *(const ulonglong2*)(xr3 + p4 * 4);
        if (rg == 0) {
            fadd2(rs0, x0.x); fadd2(rs0, x0.y);
            fadd2(rs1, x1.x); fadd2(rs1, x1.y);
            fadd2(rs2, x2.x); fadd2(rs2, x2.y);
            fadd2(rs3, x3.x); fadd2(rs3, x3.y);
        }
        const u64* vp = vts2 + (2 * p4) * 16 + r0;
        ulonglong2 va = *(const ulonglong2*)(vp);        // p2=2p4,  r0..r0+1
        ulonglong2 vb = *(const ulonglong2*)(vp + 2);    // p2=2p4,  r0+2..r0+3
        ulonglong2 vc = *(const ulonglong2*)(vp + 16);   // p2=2p4+1
        ulonglong2 vd = *(const ulonglong2*)(vp + 18);

        ffma2(a0[0], x0.x, va.x); ffma2(a0[1], x0.x, va.y);
        ffma2(a0[2], x0.x, vb.x); ffma2(a0[3], x0.x, vb.y);
        ffma2(a1[0], x1.x, va.x); ffma2(a1[1], x1.x, va.y);
        ffma2(a1[2], x1.x, vb.x); ffma2(a1[3], x1.x, vb.y);
        ffma2(a2[0], x2.x, va.x); ffma2(a2[1], x2.x, va.y);
        ffma2(a2[2], x2.x, vb.x); ffma2(a2[3], x2.x, vb.y);
        ffma2(a3[0], x3.x, va.x); ffma2(a3[1], x3.x, va.y);
        ffma2(a3[2], x3.x, vb.x); ffma2(a3[3], x3.x, vb.y);

        ffma2(a0[0], x0.y, vc.x); ffma2(a0[1], x0.y, vc.y);
        ffma2(a0[2], x0.y, vd.x); ffma2(a0[3], x0.y, vd.y);
        ffma2(a1[0], x1.y, vc.x); ffma2(a1[1], x1.y, vc.y);
        ffma2(a1[2], x1.y, vd.x); ffma2(a1[3], x1.y, vd.y);
        ffma2(a2[0], x2.y, vc.x); ffma2(a2[1], x2.y, vc.y);
        ffma2(a2[2], x2.y, vd.x); ffma2(a2[3], x2.y, vd.y);
        ffma2(a3[0], x3.y, vc.x); ffma2(a3[1], x3.y, vc.y);
        ffma2(a3[2], x3.y, vd.x); ffma2(a3[3], x3.y, vd.y);
    }

    // 4) Store T: [qt][ib][r][m] -> coalesced STG.32 per (row-group, rank)
    {
        float* base = g_T + ((size_t)((qt * NB + ib) * RANK)) * M_TOTAL + row0 + mg;
        float lo, hi;
        #pragma unroll
        for (int k = 0; k < 4; ++k) {
            size_t roff = (size_t)(r0 + k) * M_TOTAL;
            unpack2(a0[k], lo, hi); base[roff]       = lo + hi;
            unpack2(a1[k], lo, hi); base[roff + 64]  = lo + hi;
            unpack2(a2[k], lo, hi); base[roff + 128] = lo + hi;
            unpack2(a3[k], lo, hi); base[roff + 192] = lo + hi;
        }
    }
    if (rg == 0) {
        float lo, hi;
        unpack2(rs0, lo, hi); g_rsp[(size_t)(row0 + mg)       * (NB * NQ) + ib * NQ + qt] = lo + hi;
        unpack2(rs1, lo, hi); g_rsp[(size_t)(row0 + mg + 64)  * (NB * NQ) + ib * NQ + qt] = lo + hi;
        unpack2(rs2, lo, hi); g_rsp[(size_t)(row0 + mg + 128) * (NB * NQ) + ib * NQ + qt] = lo + hi;
        unpack2(rs3, lo, hi); g_rsp[(size_t)(row0 + mg + 192) * (NB * NQ) + ib * NQ + qt] = lo + hi;
    }
}

// ================= Kernel Z =================
// For each rank r: Z_r[o][m] = sum_i S[o][i][r] * (sum_qt T_qt)[i][r][m]
__global__ void __launch_bounds__(256)
kernelZ(const float* __restrict__ S)
{
    __shared__ float Ts[NB * 256];     // [i][m] 16 KB
    __shared__ float Ss[8 * NB];       // S[o][i] at this r, 8 o's

    const int r   = blockIdx.x;
    const int oh  = blockIdx.y & 1;    // o-half
    const int m0  = (blockIdx.y >> 1) * 256;
    const int tid = threadIdx.x;

    if (tid < 128) {
        int o = oh * 8 + (tid >> 4);
        int i = tid & 15;
        Ss[tid] = S[(o * NB + i) * RANK + r];
    }

    const float4* gT4 = (const float4*)g_T;
    const size_t qs = (size_t)NB * RANK * (M_TOTAL / 4);   // float4 per strip
    #pragma unroll
    for (int k = 0; k < 4; ++k) {
        int idx = tid + k * 256;       // 0..1023 over i(16) x c4(64)
        int i   = idx >> 6;
        int c4  = idx & 63;
        size_t base = ((size_t)i * RANK + r) * (M_TOTAL / 4) + (m0 / 4) + c4;
        float4 a = gT4[base];
        #pragma unroll
        for (int q = 1; q < NQ; ++q) {
            float4 b = gT4[base + q * qs];
            a.x += b.x; a.y += b.y; a.z += b.z; a.w += b.w;
        }
        ((float4*)(Ts + i * 256))[c4] = a;
    }
    __syncthreads();

    float t[NB];
    #pragma unroll
    for (int i = 0; i < NB; ++i) t[i] = Ts[i * 256 + tid];   // conflict-free

    #pragma unroll
    for (int oo = 0; oo < 8; ++oo) {
        float z = 0.f;
        #pragma unroll
        for (int i = 0; i < NB; ++i) z = fmaf(t[i], Ss[oo * 16 + i], z);
        g_Z[((size_t)((oh * 8 + oo) * RANK + r)) * M_TOTAL + m0 + tid] = z;  // coalesced
    }
}

// ================= Kernel B: out = Z @ U + (1+rowsum)*bias =================
#define ROWS_B  32
#define ZS2     34      // u64 stride (even -> 16B-aligned ull2 loads)

__global__ void __launch_bounds__(256)
kernelB(const float* __restrict__ U, const float* __restrict__ bias,
        float* __restrict__ out)
{
    __shared__ float Us[RANK * BLK];       // 16 KB
    __shared__ u64   Zt2[RANK * ZS2];      // (z,z) duplicated pairs, [r][m]
    __shared__ float rs[ROWS_B];

    const int o    = blockIdx.x;
    const int row0 = blockIdx.y * ROWS_B;
    const int tid  = threadIdx.x;

    const float4* Ug4 = (const float4*)(U + (size_t)o * (RANK * BLK));
    #pragma unroll
    for (int i = tid; i < 1024; i += 256) ((float4*)Us)[i] = Ug4[i];

    // Zt2 fill from g_Z[o][r][m] (m-contiguous)
    {
        int r = tid >> 5;         // 0..7
        int m = tid & 31;
        float z0 = g_Z[((size_t)(o * RANK + r))     * M_TOTAL + row0 + m];
        float z1 = g_Z[((size_t)(o * RANK + r + 8)) * M_TOTAL + row0 + m];
        Zt2[r * ZS2 + m]       = pack2(z0, z0);
        Zt2[(r + 8) * ZS2 + m] = pack2(z1, z1);
    }
    if (tid < ROWS_B) {
        const float4* rp = (const float4*)(g_rsp + (size_t)(row0 + tid) * (NB * NQ));
        float s = 1.0f;
        #pragma unroll
        for (int c = 0; c < 32; ++c) {
            float4 v = rp[c];
            s += (v.x + v.y) + (v.z + v.w);
        }
        rs[tid] = s;
    }
    __syncthreads();

    const int mg = tid >> 5;        // 0..7 -> rows m0..m0+3
    const int qg = tid & 31;        // q = qg*4 and 128+qg*4
    const int m0 = mg * 4;

    const float4* b4 = (const float4*)bias;
    float4 ba = b4[o * 64 + qg];
    float4 bb = b4[o * 64 + 32 + qg];

    ulonglong2 Aa[4], Ab[4];
    #pragma unroll
    for (int j = 0; j < 4; ++j) {
        float r = rs[m0 + j];
        Aa[j].x = pack2(r * ba.x, r * ba.y);
        Aa[j].y = pack2(r * ba.z, r * ba.w);
        Ab[j].x = pack2(r * bb.x, r * bb.y);
        Ab[j].y = pack2(r * bb.z, r * bb.w);
    }

    #pragma unroll
    for (int r = 0; r < RANK; ++r) {
        const u64* zp = Zt2 + r * ZS2 + m0;
        ulonglong2 z01 = *(const ulonglong2*)(zp);       // broadcast LDS.128
        ulonglong2 z23 = *(const ulonglong2*)(zp + 2);
        u64 q0 = z01.x, q1 = z01.y, q2 = z23.x, q3 = z23.y;
        ulonglong2 ua = *(const ulonglong2*)(Us + r * 256 + qg * 4);
        ulonglong2 ub = *(const ulonglong2*)(Us + r * 256 + 128 + qg * 4);
        ffma2(Aa[0].x, q0, ua.x); ffma2(Aa[0].y, q0, ua.y);
        ffma2(Ab[0].x, q0, ub.x); ffma2(Ab[0].y, q0, ub.y);
        ffma2(Aa[1].x, q1, ua.x); ffma2(Aa[1].y, q1, ua.y);
        ffma2(Ab[1].x, q1, ub.x); ffma2(Ab[1].y, q1, ub.y);
        ffma2(Aa[2].x, q2, ua.x); ffma2(Aa[2].y, q2, ua.y);
        ffma2(Ab[2].x, q2, ub.x); ffma2(Ab[2].y, q2, ub.y);
        ffma2(Aa[3].x, q3, ua.x); ffma2(Aa[3].y, q3, ua.y);
        ffma2(Ab[3].x, q3, ub.x); ffma2(Ab[3].y, q3, ub.y);
    }

    size_t ob = (size_t)(row0 + m0) * OUT_DIM + o * 256 + qg * 4;
    #pragma unroll
    for (int j = 0; j < 4; ++j) {
        *(ulonglong2*)(out + ob + (size_t)j * OUT_DIM)       = Aa[j];
        *(ulonglong2*)(out + ob + (size_t)j * OUT_DIM + 128) = Ab[j];
    }
}

extern "C" void kernel_launch(void* const* d_in, const int* in_sizes, int n_in,
                              void* d_out, int out_size)
{
    const float* x    = (const float*)d_in[0];
    const float* S    = (const float*)d_in[1];
    const float* U    = (const float*)d_in[2];
    const float* Vt   = (const float*)d_in[3];
    const float* bias = (const float*)d_in[4];
    float* out = (float*)d_out;

    kernelA<<<dim3(NB * NQ, M_TOTAL / ROWS_A), 256>>>(x, Vt);
    kernelZ<<<dim3(RANK, 16), 256>>>(S);
    kernelB<<<dim3(NB, M_TOTAL / ROWS_B), 256>>>(U, bias, out);
}

// round 15
// speedup vs baseline: 1.0591x; 1.0524x over previous
#include <cuda_runtime.h>

#define M_TOTAL 2048
#define IN_DIM  4096
#define OUT_DIM 4096
#define NB      16
#define RANK    16
#define BLK     256
#define NQ      4             // T strips (qt), 64 p each

typedef unsigned long long u64;

// Scratch (__device__ globals per allocation rules)
__device__ float g_T[NQ * NB * RANK * M_TOTAL];   // [qt][ib][r][m]  8 MB, m contiguous
__device__ float g_Z[NB * RANK * M_TOTAL];        // [o][r][m]       2 MB, m contiguous
__device__ float g_rsp[M_TOTAL * NB * NQ];        // [m][ib*4+qt]    1 MB

// ---------- f32x2 packed helpers ----------
__device__ __forceinline__ u64 pack2(float lo, float hi) {
    u64 r; asm("mov.b64 %0, {%1, %2};" : "=l"(r) : "f"(lo), "f"(hi)); return r;
}
__device__ __forceinline__ void unpack2(u64 p, float& lo, float& hi) {
    asm("mov.b64 {%0, %1}, %2;" : "=f"(lo), "=f"(hi) : "l"(p));
}
__device__ __forceinline__ void ffma2(u64& d, u64 a, u64 b) {
    asm("fma.rn.f32x2 %0, %1, %2, %0;" : "+l"(d) : "l"(a), "l"(b));
}
__device__ __forceinline__ void fadd2(u64& d, u64 a) {
    asm("add.rn.f32x2 %0, %0, %1;" : "+l"(d) : "l"(a));
}

// ---------- cp.async helpers ----------
__device__ __forceinline__ unsigned smem_u32(const void* p) {
    unsigned a;
    asm("{ .reg .u64 t; cvta.to.shared.u64 t, %1; cvt.u32.u64 %0, t; }" : "=r"(a) : "l"(p));
    return a;
}
__device__ __forceinline__ void cp_async16(unsigned dst, const void* src) {
    asm volatile("cp.async.ca.shared.global [%0], [%1], 16;" :: "r"(dst), "l"(src));
}
__device__ __forceinline__ void cp_commit() {
    asm volatile("cp.async.commit_group;");
}
__device__ __forceinline__ void cp_wait1() {
    asm volatile("cp.async.wait_group 1;");
}
__device__ __forceinline__ void cp_wait0() {
    asm volatile("cp.async.wait_group 0;");
}

// ================= Kernel A =================
// CTA = (ib, qt) x 128 rows; KA=64 cols as two 32-col pieces, double-buffered:
// both fills burst-issued up front, piece1 streams while piece0 computes.
// Accumulate both pieces in registers -> ONE T store (T stays 8 MB).
#define ROWS_A  128
#define PSTR    36            // 32 + 4 pad floats per piece row

__global__ void __launch_bounds__(256)
kernelA(const float* __restrict__ x, const float* __restrict__ Vt)
{
    __shared__ float xs[2][ROWS_A * PSTR];     // 2 x 18.4 KB
    __shared__ u64   vts2[32 * RANK];          // [p2 0..31][r]  4 KB (64 p pairs)

    const int qt   = blockIdx.x & 3;           // strip (p offset qt*64)
    const int ib   = blockIdx.x >> 2;
    const int row0 = blockIdx.y * ROWS_A;
    const int tid  = threadIdx.x;

    const float4* xg4 = (const float4*)x;
    unsigned xb[2] = { smem_u32(&xs[0][0]), smem_u32(&xs[1][0]) };

    // Burst-issue BOTH piece fills immediately (separate groups)
    #pragma unroll
    for (int h = 0; h < 2; ++h) {
        #pragma unroll
        for (int k = 0; k < 4; ++k) {
            int idx = tid + k * 256;       // 0..1023
            int m   = idx >> 3;
            int c4  = idx & 7;
            const float4* src = xg4 + ((size_t)(row0 + m) * (IN_DIM / 4)
                                       + ib * 64 + qt * 16 + h * 8 + c4);
            cp_async16(xb[h] + (m * PSTR + c4 * 4) * 4, src);
        }
        cp_commit();
    }

    // Stage all 64 p's worth of Vt pairs while fills stream (2 per thread)
    #pragma unroll
    for (int k = 0; k < 2; ++k) {
        int p2 = (tid >> 4) + k * 16;      // 0..31
        int r  = tid & 15;
        const float* vg = Vt + ((size_t)ib * BLK + qt * 64 + 2 * p2) * RANK + r;
        vts2[p2 * 16 + r] = pack2(vg[0], vg[RANK]);
    }

    const int mg = tid & 127;              // row
    const int rg = tid >> 7;               // warp-uniform rank half
    const int r0 = rg * 8;

    u64 acc[8];
    #pragma unroll
    for (int k = 0; k < 8; ++k) acc[k] = 0ULL;
    u64 rs = 0ULL;

    #pragma unroll
    for (int h = 0; h < 2; ++h) {
        if (h == 0) cp_wait1();            // piece 0 landed (group 1 may be in flight)
        else        cp_wait0();            // piece 1 landed
        __syncthreads();                   // cross-thread visibility

        const float* xr = &xs[h][mg * PSTR];
        const u64*   vb = vts2 + (h * 16) * 16;   // p2 base for this piece

        #pragma unroll
        for (int p4 = 0; p4 < 8; ++p4) {
            ulonglong2 xa = *(const ulonglong2*)(xr + p4 * 4);   // (p0,p1),(p2,p3)
            if (rg == 0) { fadd2(rs, xa.x); fadd2(rs, xa.y); }
            const u64* v0 = vb + (2 * p4) * 16 + r0;
            {
                ulonglong2 a = *(const ulonglong2*)(v0);
                ulonglong2 b = *(const ulonglong2*)(v0 + 2);
                ulonglong2 c = *(const ulonglong2*)(v0 + 4);
                ulonglong2 d = *(const ulonglong2*)(v0 + 6);
                ffma2(acc[0], xa.x, a.x); ffma2(acc[1], xa.x, a.y);
                ffma2(acc[2], xa.x, b.x); ffma2(acc[3], xa.x, b.y);
                ffma2(acc[4], xa.x, c.x); ffma2(acc[5], xa.x, c.y);
                ffma2(acc[6], xa.x, d.x); ffma2(acc[7], xa.x, d.y);
            }
            const u64* v1 = v0 + 16;
            {
                ulonglong2 a = *(const ulonglong2*)(v1);
                ulonglong2 b = *(const ulonglong2*)(v1 + 2);
                ulonglong2 c = *(const ulonglong2*)(v1 + 4);
                ulonglong2 d = *(const ulonglong2*)(v1 + 6);
                ffma2(acc[0], xa.y, a.x); ffma2(acc[1], xa.y, a.y);
                ffma2(acc[2], xa.y, b.x); ffma2(acc[3], xa.y, b.y);
                ffma2(acc[4], xa.y, c.x); ffma2(acc[5], xa.y, c.y);
                ffma2(acc[6], xa.y, d.x); ffma2(acc[7], xa.y, d.y);
            }
        }
    }

    // Store T once: [qt][ib][r][m] -> coalesced STG.32 per rank
    {
        float* base = g_T + ((size_t)((qt * NB + ib) * RANK)) * M_TOTAL + row0 + mg;
        #pragma unroll
        for (int k = 0; k < 8; ++k) {
            float lo, hi;
            unpack2(acc[k], lo, hi);
            base[(size_t)(r0 + k) * M_TOTAL] = lo + hi;
        }
    }
    if (rg == 0) {
        float lo, hi;
        unpack2(rs, lo, hi);
        g_rsp[(size_t)(row0 + mg) * (NB * NQ) + ib * NQ + qt] = lo + hi;
    }
}

// ================= Kernel Z =================
// For each rank r: Z_r[o][m] = sum_i S[o][i][r] * (sum_qt T_qt)[i][r][m]
__global__ void __launch_bounds__(256)
kernelZ(const float* __restrict__ S)
{
    __shared__ float Ts[NB * 256];     // [i][m] 16 KB
    __shared__ float Ss[8 * NB];       // S[o][i] at this r, 8 o's

    const int r   = blockIdx.x;
    const int oh  = blockIdx.y & 1;    // o-half
    const int m0  = (blockIdx.y >> 1) * 256;
    const int tid = threadIdx.x;

    if (tid < 128) {
        int o = oh * 8 + (tid >> 4);
        int i = tid & 15;
        Ss[tid] = S[(o * NB + i) * RANK + r];
    }

    const float4* gT4 = (const float4*)g_T;
    const size_t qs = (size_t)NB * RANK * (M_TOTAL / 4);   // float4 per strip
    #pragma unroll
    for (int k = 0; k < 4; ++k) {
        int idx = tid + k * 256;       // 0..1023 over i(16) x c4(64)
        int i   = idx >> 6;
        int c4  = idx & 63;
        size_t base = ((size_t)i * RANK + r) * (M_TOTAL / 4) + (m0 / 4) + c4;
        float4 a = gT4[base];
        #pragma unroll
        for (int q = 1; q < NQ; ++q) {
            float4 b = gT4[base + q * qs];
            a.x += b.x; a.y += b.y; a.z += b.z; a.w += b.w;
        }
        ((float4*)(Ts + i * 256))[c4] = a;
    }
    __syncthreads();

    float t[NB];
    #pragma unroll
    for (int i = 0; i < NB; ++i) t[i] = Ts[i * 256 + tid];   // conflict-free

    #pragma unroll
    for (int oo = 0; oo < 8; ++oo) {
        float z = 0.f;
        #pragma unroll
        for (int i = 0; i < NB; ++i) z = fmaf(t[i], Ss[oo * 16 + i], z);
        g_Z[((size_t)((oh * 8 + oo) * RANK + r)) * M_TOTAL + m0 + tid] = z;  // coalesced
    }
}

// ================= Kernel B: out = Z @ U + (1+rowsum)*bias =================
#define ROWS_B  32
#define ZS2     34      // u64 stride (even -> 16B-aligned ull2 loads)

__global__ void __launch_bounds__(256)
kernelB(const float* __restrict__ U, const float* __restrict__ bias,
        float* __restrict__ out)
{
    __shared__ float Us[RANK * BLK];       // 16 KB
    __shared__ u64   Zt2[RANK * ZS2];      // (z,z) duplicated pairs, [r][m]
    __shared__ float rs[ROWS_B];

    const int o    = blockIdx.x;
    const int row0 = blockIdx.y * ROWS_B;
    const int tid  = threadIdx.x;

    const float4* Ug4 = (const float4*)(U + (size_t)o * (RANK * BLK));
    #pragma unroll
    for (int i = tid; i < 1024; i += 256) ((float4*)Us)[i] = Ug4[i];

    // Zt2 fill from g_Z[o][r][m] (m-contiguous)
    {
        int r = tid >> 5;         // 0..7
        int m = tid & 31;
        float z0 = g_Z[((size_t)(o * RANK + r))     * M_TOTAL + row0 + m];
        float z1 = g_Z[((size_t)(o * RANK + r + 8)) * M_TOTAL + row0 + m];
        Zt2[r * ZS2 + m]       = pack2(z0, z0);
        Zt2[(r + 8) * ZS2 + m] = pack2(z1, z1);
    }
    if (tid < ROWS_B) {
        const float4* rp = (const float4*)(g_rsp + (size_t)(row0 + tid) * (NB * NQ));
        float s = 1.0f;
        #pragma unroll
        for (int c = 0; c < 16; ++c) {
            float4 v = rp[c];
            s += (v.x + v.y) + (v.z + v.w);
        }
        rs[tid] = s;
    }
    __syncthreads();

    const int mg = tid >> 5;        // 0..7 -> rows m0..m0+3
    const int qg = tid & 31;        // q = qg*4 and 128+qg*4
    const int m0 = mg * 4;

    const float4* b4 = (const float4*)bias;
    float4 ba = b4[o * 64 + qg];
    float4 bb = b4[o * 64 + 32 + qg];

    ulonglong2 Aa[4], Ab[4];
    #pragma unroll
    for (int j = 0; j < 4; ++j) {
        float r = rs[m0 + j];
        Aa[j].x = pack2(r * ba.x, r * ba.y);
        Aa[j].y = pack2(r * ba.z, r * ba.w);
        Ab[j].x = pack2(r * bb.x, r * bb.y);
        Ab[j].y = pack2(r * bb.z, r * bb.w);
    }

    #pragma unroll
    for (int r = 0; r < RANK; ++r) {
        const u64* zp = Zt2 + r * ZS2 + m0;
        ulonglong2 z01 = *(const ulonglong2*)(zp);       // broadcast LDS.128
        ulonglong2 z23 = *(const ulonglong2*)(zp + 2);
        u64 q0 = z01.x, q1 = z01.y, q2 = z23.x, q3 = z23.y;
        ulonglong2 ua = *(const ulonglong2*)(Us + r * 256 + qg * 4);
        ulonglong2 ub = *(const ulonglong2*)(Us + r * 256 + 128 + qg * 4);
        ffma2(Aa[0].x, q0, ua.x); ffma2(Aa[0].y, q0, ua.y);
        ffma2(Ab[0].x, q0, ub.x); ffma2(Ab[0].y, q0, ub.y);
        ffma2(Aa[1].x, q1, ua.x); ffma2(Aa[1].y, q1, ua.y);
        ffma2(Ab[1].x, q1, ub.x); ffma2(Ab[1].y, q1, ub.y);
        ffma2(Aa[2].x, q2, ua.x); ffma2(Aa[2].y, q2, ua.y);
        ffma2(Ab[2].x, q2, ub.x); ffma2(Ab[2].y, q2, ub.y);
        ffma2(Aa[3].x, q3, ua.x); ffma2(Aa[3].y, q3, ua.y);
        ffma2(Ab[3].x, q3, ub.x); ffma2(Ab[3].y, q3, ub.y);
    }

    size_t ob = (size_t)(row0 + m0) * OUT_DIM + o * 256 + qg * 4;
    #pragma unroll
    for (int j = 0; j < 4; ++j) {
        *(ulonglong2*)(out + ob + (size_t)j * OUT_DIM)       = Aa[j];
        *(ulonglong2*)(out + ob + (size_t)j * OUT_DIM + 128) = Ab[j];
    }
}

extern "C" void kernel_launch(void* const* d_in, const int* in_sizes, int n_in,
                              void* d_out, int out_size)
{
    const float* x    = (const float*)d_in[0];
    const float* S    = (const float*)d_in[1];
    const float* U    = (const float*)d_in[2];
    const float* Vt   = (const float*)d_in[3];
    const float* bias = (const float*)d_in[4];
    float* out = (float*)d_out;

    kernelA<<<dim3(NB * NQ, M_TOTAL / ROWS_A), 256>>>(x, Vt);
    kernelZ<<<dim3(RANK, 16), 256>>>(S);
    kernelB<<<dim3(NB, M_TOTAL / ROWS_B), 256>>>(U, bias, out);
}

// round 16
// speedup vs baseline: 1.0693x; 1.0096x over previous
#include <cuda_runtime.h>

#define M_TOTAL 2048
#define IN_DIM  4096
#define OUT_DIM 4096
#define NB      16
#define RANK    16
#define BLK     256
#define NQ      8             // eighth strips of 32 p
#define KA      32

typedef unsigned long long u64;

// Scratch (__device__ globals per allocation rules)
__device__ float g_T[NQ * NB * RANK * M_TOTAL];   // [qt][ib][r][m]  16 MB, m contiguous
__device__ float g_Z[NB * RANK * M_TOTAL];        // [o][r][m]       2 MB, m contiguous
__device__ float g_rsp[M_TOTAL * NB * NQ];        // [m][ib*8+qt]    1 MB

// ---------- f32x2 packed helpers ----------
__device__ __forceinline__ u64 pack2(float lo, float hi) {
    u64 r; asm("mov.b64 %0, {%1, %2};" : "=l"(r) : "f"(lo), "f"(hi)); return r;
}
__device__ __forceinline__ void unpack2(u64 p, float& lo, float& hi) {
    asm("mov.b64 {%0, %1}, %2;" : "=f"(lo), "=f"(hi) : "l"(p));
}
__device__ __forceinline__ void ffma2(u64& d, u64 a, u64 b) {
    asm("fma.rn.f32x2 %0, %1, %2, %0;" : "+l"(d) : "l"(a), "l"(b));
}
__device__ __forceinline__ void fadd2(u64& d, u64 a) {
    asm("add.rn.f32x2 %0, %0, %1;" : "+l"(d) : "l"(a));
}

// ---------- cp.async helpers ----------
__device__ __forceinline__ unsigned smem_u32(const void* p) {
    unsigned a;
    asm("{ .reg .u64 t; cvta.to.shared.u64 t, %1; cvt.u32.u64 %0, t; }" : "=r"(a) : "l"(p));
    return a;
}
__device__ __forceinline__ void cp_async16(unsigned dst, const void* src) {
    asm volatile("cp.async.ca.shared.global [%0], [%1], 16;" :: "r"(dst), "l"(src));
}
__device__ __forceinline__ void cp_commit() {
    asm volatile("cp.async.commit_group;");
}
__device__ __forceinline__ void cp_wait0() {
    asm volatile("cp.async.wait_group 0;");
}

// ================= Kernel A (R14 — best measured: 15.1us) =================
// One cp.async burst, one barrier, grid 1024, smem 39KB, 4 rows x 4 ranks tile.
#define ROWS_A  256
#define PSTR    36            // 32 + 4 pad floats; conflict-free LDS.128

__global__ void __launch_bounds__(256)
kernelA(const float* __restrict__ x, const float* __restrict__ Vt)
{
    __shared__ float xs[ROWS_A * PSTR];        // 36.9 KB
    __shared__ u64   vts2[(KA / 2) * RANK];    // [p2][r] 2 KB

    const int qt   = blockIdx.x & 7;           // eighth 0..7 (p offset qt*32)
    const int ib   = blockIdx.x >> 3;          // input block
    const int row0 = blockIdx.y * ROWS_A;
    const int tid  = threadIdx.x;

    // 1) Issue ALL x fills immediately (one group, 2048 float4s = 32 KB)
    const float4* xg4 = (const float4*)x;
    unsigned xs_base = smem_u32(xs);
    #pragma unroll
    for (int k = 0; k < 8; ++k) {
        int idx = tid + k * 256;          // 0..2047
        int m   = idx >> 3;
        int c4  = idx & 7;
        const float4* src = xg4 + ((size_t)(row0 + m) * (IN_DIM / 4)
                                   + ib * 64 + qt * 8 + c4);
        cp_async16(xs_base + (m * PSTR + c4 * 4) * 4, src);
    }
    cp_commit();

    // 2) Stage Vt pairs while the async fill streams in
    {
        int p2 = tid >> 4;                // 0..15
        int r  = tid & 15;
        const float* vg = Vt + ((size_t)ib * BLK + qt * KA + 2 * p2) * RANK + r;
        vts2[p2 * 16 + r] = pack2(vg[0], vg[RANK]);
    }

    cp_wait0();
    __syncthreads();                      // the ONLY barrier

    // 3) Compute: 4 rows x 4 ranks per thread, f32x2 over p, 8 p4-iters
    const int mg = tid & 63;              // rows mg, +64, +128, +192
    const int rg = tid >> 6;              // 0..3 warp-uniform -> ranks rg*4..+3
    const int r0 = rg * 4;
    const float* xr0 = xs + mg * PSTR;
    const float* xr1 = xs + (mg + 64) * PSTR;
    const float* xr2 = xs + (mg + 128) * PSTR;
    const float* xr3 = xs + (mg + 192) * PSTR;

    u64 a0[4], a1[4], a2[4], a3[4];
    #pragma unroll
    for (int k = 0; k < 4; ++k) { a0[k] = 0ULL; a1[k] = 0ULL; a2[k] = 0ULL; a3[k] = 0ULL; }
    u64 rs0 = 0ULL, rs1 = 0ULL, rs2 = 0ULL, rs3 = 0ULL;

    #pragma unroll
    for (int p4 = 0; p4 < 8; ++p4) {
        ulonglong2 x0 = *(const ulonglong2*)(xr0 + p4 * 4);   // (p0,p1),(p2,p3)
        ulonglong2 x1 = *(const ulonglong2*)(xr1 + p4 * 4);
        ulonglong2 x2 = *(const ulonglong2*)(xr2 + p4 * 4);
        ulonglong2 x3 = *(const ulonglong2*)(xr3 + p4 * 4);
        if (rg == 0) {
            fadd2(rs0, x0.x); fadd2(rs0, x0.y);
            fadd2(rs1, x1.x); fadd2(rs1, x1.y);
            fadd2(rs2, x2.x); fadd2(rs2, x2.y);
            fadd2(rs3, x3.x); fadd2(rs3, x3.y);
        }
        const u64* vp = vts2 + (2 * p4) * 16 + r0;
        ulonglong2 va = *(const ulonglong2*)(vp);        // p2=2p4,  r0..r0+1
        ulonglong2 vb = *(const ulonglong2*)(vp + 2);    // p2=2p4,  r0+2..r0+3
        ulonglong2 vc = *(const ulonglong2*)(vp + 16);   // p2=2p4+1
        ulonglong2 vd = *(const ulonglong2*)(vp + 18);

        ffma2(a0[0], x0.x, va.x); ffma2(a0[1], x0.x, va.y);
        ffma2(a0[2], x0.x, vb.x); ffma2(a0[3], x0.x, vb.y);
        ffma2(a1[0], x1.x, va.x); ffma2(a1[1], x1.x, va.y);
        ffma2(a1[2], x1.x, vb.x); ffma2(a1[3], x1.x, vb.y);
        ffma2(a2[0], x2.x, va.x); ffma2(a2[1], x2.x, va.y);
        ffma2(a2[2], x2.x, vb.x); ffma2(a2[3], x2.x, vb.y);
        ffma2(a3[0], x3.x, va.x); ffma2(a3[1], x3.x, va.y);
        ffma2(a3[2], x3.x, vb.x); ffma2(a3[3], x3.x, vb.y);

        ffma2(a0[0], x0.y, vc.x); ffma2(a0[1], x0.y, vc.y);
        ffma2(a0[2], x0.y, vd.x); ffma2(a0[3], x0.y, vd.y);
        ffma2(a1[0], x1.y, vc.x); ffma2(a1[1], x1.y, vc.y);
        ffma2(a1[2], x1.y, vd.x); ffma2(a1[3], x1.y, vd.y);
        ffma2(a2[0], x2.y, vc.x); ffma2(a2[1], x2.y, vc.y);
        ffma2(a2[2], x2.y, vd.x); ffma2(a2[3], x2.y, vd.y);
        ffma2(a3[0], x3.y, vc.x); ffma2(a3[1], x3.y, vc.y);
        ffma2(a3[2], x3.y, vd.x); ffma2(a3[3], x3.y, vd.y);
    }

    // 4) Store T: [qt][ib][r][m] -> coalesced STG.32 per (row-group, rank)
    {
        float* base = g_T + ((size_t)((qt * NB + ib) * RANK)) * M_TOTAL + row0 + mg;
        float lo, hi;
        #pragma unroll
        for (int k = 0; k < 4; ++k) {
            size_t roff = (size_t)(r0 + k) * M_TOTAL;
            unpack2(a0[k], lo, hi); base[roff]       = lo + hi;
            unpack2(a1[k], lo, hi); base[roff + 64]  = lo + hi;
            unpack2(a2[k], lo, hi); base[roff + 128] = lo + hi;
            unpack2(a3[k], lo, hi); base[roff + 192] = lo + hi;
        }
    }
    if (rg == 0) {
        float lo, hi;
        unpack2(rs0, lo, hi); g_rsp[(size_t)(row0 + mg)       * (NB * NQ) + ib * NQ + qt] = lo + hi;
        unpack2(rs1, lo, hi); g_rsp[(size_t)(row0 + mg + 64)  * (NB * NQ) + ib * NQ + qt] = lo + hi;
        unpack2(rs2, lo, hi); g_rsp[(size_t)(row0 + mg + 128) * (NB * NQ) + ib * NQ + qt] = lo + hi;
        unpack2(rs3, lo, hi); g_rsp[(size_t)(row0 + mg + 192) * (NB * NQ) + ib * NQ + qt] = lo + hi;
    }
}

// ================= Kernel Z (rewritten: T read ONCE, high MLP) =================
// grid (16 r, 16 m-chunks of 128). Each CTA qt-sums its T slice (16 independent
// loads in flight per thread), then computes ALL 16 o's from an 8 KB smem tile.
__global__ void __launch_bounds__(256)
kernelZ(const float* __restrict__ S)
{
    __shared__ float Ts[NB * 128];     // [i][m] 8 KB
    __shared__ float Ss[NB * NB];      // S[o][i] at this r

    const int r   = blockIdx.x;
    const int m0  = blockIdx.y * 128;
    const int tid = threadIdx.x;

    Ss[tid] = S[tid * RANK + r];       // tid = o*16+i

    const float4* gT4 = (const float4*)g_T;
    const size_t qs = (size_t)NB * RANK * (M_TOTAL / 4);   // float4 per strip
    #pragma unroll
    for (int k = 0; k < 2; ++k) {
        int idx = tid + k * 256;       // 0..511 over i(16) x c4(32)
        int i   = idx >> 5;
        int c4  = idx & 31;
        size_t base = ((size_t)i * RANK + r) * (M_TOTAL / 4) + (m0 / 4) + c4;
        float4 a = gT4[base];
        #pragma unroll
        for (int q = 1; q < NQ; ++q) {
            float4 b = gT4[base + q * qs];
            a.x += b.x; a.y += b.y; a.z += b.z; a.w += b.w;
        }
        ((float4*)(Ts + i * 128))[c4] = a;
    }
    __syncthreads();

    const int m  = tid & 127;
    const int oh = tid >> 7;           // o-half (0/1)

    float t[NB];
    #pragma unroll
    for (int i = 0; i < NB; ++i) t[i] = Ts[i * 128 + m];   // conflict-free

    #pragma unroll
    for (int oo = 0; oo < 8; ++oo) {
        int o = oh * 8 + oo;
        float z = 0.f;
        #pragma unroll
        for (int i = 0; i < NB; ++i) z = fmaf(t[i], Ss[o * 16 + i], z);
        g_Z[((size_t)(o * RANK + r)) * M_TOTAL + m0 + m] = z;   // coalesced
    }
}

// ================= Kernel B: out = Z @ U + (1+rowsum)*bias =================
#define ROWS_B  32
#define ZS2     34      // u64 stride (even -> 16B-aligned ull2 loads)

__global__ void __launch_bounds__(256)
kernelB(const float* __restrict__ U, const float* __restrict__ bias,
        float* __restrict__ out)
{
    __shared__ float Us[RANK * BLK];       // 16 KB
    __shared__ u64   Zt2[RANK * ZS2];      // (z,z) duplicated pairs, [r][m]
    __shared__ float rs[ROWS_B];

    const int o    = blockIdx.x;
    const int row0 = blockIdx.y * ROWS_B;
    const int tid  = threadIdx.x;

    const float4* Ug4 = (const float4*)(U + (size_t)o * (RANK * BLK));
    #pragma unroll
    for (int i = tid; i < 1024; i += 256) ((float4*)Us)[i] = Ug4[i];

    // Zt2 fill from g_Z[o][r][m] (m-contiguous)
    {
        int r = tid >> 5;         // 0..7
        int m = tid & 31;
        float z0 = g_Z[((size_t)(o * RANK + r))     * M_TOTAL + row0 + m];
        float z1 = g_Z[((size_t)(o * RANK + r + 8)) * M_TOTAL + row0 + m];
        Zt2[r * ZS2 + m]       = pack2(z0, z0);
        Zt2[(r + 8) * ZS2 + m] = pack2(z1, z1);
    }
    if (tid < ROWS_B) {
        const float4* rp = (const float4*)(g_rsp + (size_t)(row0 + tid) * (NB * NQ));
        float s = 1.0f;
        #pragma unroll
        for (int c = 0; c < 32; ++c) {
            float4 v = rp[c];
            s += (v.x + v.y) + (v.z + v.w);
        }
        rs[tid] = s;
    }
    __syncthreads();

    const int mg = tid >> 5;        // 0..7 -> rows m0..m0+3
    const int qg = tid & 31;        // q = qg*4 and 128+qg*4
    const int m0 = mg * 4;

    const float4* b4 = (const float4*)bias;
    float4 ba = b4[o * 64 + qg];
    float4 bb = b4[o * 64 + 32 + qg];

    ulonglong2 Aa[4], Ab[4];
    #pragma unroll
    for (int j = 0; j < 4; ++j) {
        float r = rs[m0 + j];
        Aa[j].x = pack2(r * ba.x, r * ba.y);
        Aa[j].y = pack2(r * ba.z, r * ba.w);
        Ab[j].x = pack2(r * bb.x, r * bb.y);
        Ab[j].y = pack2(r * bb.z, r * bb.w);
    }

    #pragma unroll
    for (int r = 0; r < RANK; ++r) {
        const u64* zp = Zt2 + r * ZS2 + m0;
        ulonglong2 z01 = *(const ulonglong2*)(zp);       // broadcast LDS.128
        ulonglong2 z23 = *(const ulonglong2*)(zp + 2);
        u64 q0 = z01.x, q1 = z01.y, q2 = z23.x, q3 = z23.y;
        ulonglong2 ua = *(const ulonglong2*)(Us + r * 256 + qg * 4);
        ulonglong2 ub = *(const ulonglong2*)(Us + r * 256 + 128 + qg * 4);
        ffma2(Aa[0].x, q0, ua.x); ffma2(Aa[0].y, q0, ua.y);
        ffma2(Ab[0].x, q0, ub.x); ffma2(Ab[0].y, q0, ub.y);
        ffma2(Aa[1].x, q1, ua.x); ffma2(Aa[1].y, q1, ua.y);
        ffma2(Ab[1].x, q1, ub.x); ffma2(Ab[1].y, q1, ub.y);
        ffma2(Aa[2].x, q2, ua.x); ffma2(Aa[2].y, q2, ua.y);
        ffma2(Ab[2].x, q2, ub.x); ffma2(Ab[2].y, q2, ub.y);
        ffma2(Aa[3].x, q3, ua.x); ffma2(Aa[3].y, q3, ua.y);
        ffma2(Ab[3].x, q3, ub.x); ffma2(Ab[3].y, q3, ub.y);
    }

    size_t ob = (size_t)(row0 + m0) * OUT_DIM + o * 256 + qg * 4;
    #pragma unroll
    for (int j = 0; j < 4; ++j) {
        *(ulonglong2*)(out + ob + (size_t)j * OUT_DIM)       = Aa[j];
        *(ulonglong2*)(out + ob + (size_t)j * OUT_DIM + 128) = Ab[j];
    }
}

extern "C" void kernel_launch(void* const* d_in, const int* in_sizes, int n_in,
                              void* d_out, int out_size)
{
    const float* x    = (const float*)d_in[0];
    const float* S    = (const float*)d_in[1];
    const float* U    = (const float*)d_in[2];
    const float* Vt   = (const float*)d_in[3];
    const float* bias = (const float*)d_in[4];
    float* out = (float*)d_out;

    kernelA<<<dim3(NB * NQ, M_TOTAL / ROWS_A), 256>>>(x, Vt);
    kernelZ<<<dim3(RANK, M_TOTAL / 128), 256>>>(S);
    kernelB<<<dim3(NB, M_TOTAL / ROWS_B), 256>>>(U, bias, out);
}